// round 5
// baseline (speedup 1.0000x reference)
#include <cuda_runtime.h>
#include <math.h>

#define NCLS 20
#define NA 5
#define HH 26
#define WW 26
#define NLOC 3380      // NA*HH*WW
#define NLOCP 3392     // padded to multiple of 32 for matC stride
#define NPAD 4096
#define NW 106         // ceil(NLOC/32)
#define BATCH 16
#define NMS_TH 0.45f
#define K2 0.31034482758f   // 0.45/1.45
#define PRE_TH 0.005f
#define FEAT_STRIDE 32.0f

__constant__ float c_biases[10] = {1.08f, 1.19f, 3.42f, 4.41f, 6.63f, 11.38f,
                                   9.42f, 5.11f, 16.62f, 10.52f};

// ---- device scratch (static; no allocations) ----
__device__ float g_x1[BATCH * NLOC], g_y1[BATCH * NLOC];
__device__ float g_x2[BATCH * NLOC], g_y2[BATCH * NLOC];
__device__ float g_ka[BATCH * NLOC], g_score[BATCH * NLOC];
__device__ float4 g_sbox[BATCH * NLOC];          // sorted (x1,y1,x2,y2)
__device__ float g_ska[BATCH * NLOC], g_ss[BATCH * NLOC];
__device__ int g_sidx[BATCH * NLOC];
__device__ unsigned g_alive[BATCH * NW];
// column-major suppression matrix: matC[b][w][j] = suppressor bits (i-word w) of row j
__device__ unsigned g_matC[(size_t)BATCH * NW * NLOCP];   // ~23 MB

// ============ kernel 1: decode (fully parallel) ============
__global__ void decode_kernel(const float* __restrict__ x,
                              const float* __restrict__ im_info,
                              float* __restrict__ out)
{
    const int b = blockIdx.y;
    const int loc = blockIdx.x * 128 + threadIdx.x;
    if (loc >= NLOC) return;

    const float im_h = im_info[0];
    const float im_w = im_info[1];
    const float netw = WW * FEAT_STRIDE;
    const float neth = HH * FEAT_STRIDE;
    const bool cond = (netw / im_w) < (neth / im_h);
    const float new_w = cond ? netw : im_w * neth / im_h;
    const float new_h = cond ? im_h * netw / im_w : neth;

    float* prob = out;
    float* bbox = out + (size_t)BATCH * NLOC * 21;
    const float* xb = x + (size_t)b * 125 * (HH * WW);

    int a = loc / (HH * WW);
    int rem = loc - a * (HH * WW);
    int hh = rem / WW;
    int ww = rem - hh * WW;

    float tx = xb[(2 * a) * 676 + rem];
    float ty = xb[(2 * a + 1) * 676 + rem];
    float tw = xb[(10 + 2 * a) * 676 + rem];
    float th = xb[(11 + 2 * a) * 676 + rem];
    float to = xb[(20 + a) * 676 + rem];

    float obj = 1.0f / (1.0f + expf(-to));

    float cf[NCLS];
    float m = -INFINITY;
#pragma unroll
    for (int c = 0; c < NCLS; c++) {
        cf[c] = xb[(25 + 5 * c + a) * 676 + rem];
        m = fmaxf(m, cf[c]);
    }
    float sum = 0.0f;
#pragma unroll
    for (int c = 0; c < NCLS; c++) {
        cf[c] = expf(cf[c] - m);
        sum += cf[c];
    }
    float inv = obj / sum;
    float* pr = prob + ((size_t)b * NLOC + loc) * 21;
#pragma unroll
    for (int c = 0; c < NCLS; c++) pr[c] = cf[c] * inv;

    float sx = 1.0f / (1.0f + expf(-tx));
    float sy = 1.0f / (1.0f + expf(-ty));
    float bxv = ((float)ww + sx) / (float)WW;
    float byv = ((float)hh + sy) / (float)HH;
    float bwv = c_biases[2 * a] * expf(tw) / (float)WW;
    float bhv = c_biases[2 * a + 1] * expf(th) / (float)HH;

    bxv = (bxv - (netw - new_w) * 0.5f / netw) / (new_w / netw);
    byv = (byv - (neth - new_h) * 0.5f / neth) / (new_h / neth);
    bwv = bwv * (netw / new_w);
    bhv = bhv * (neth / new_h);

    float cx = bxv * im_w, cy = byv * im_h;
    float bw2 = bwv * im_w, bh2 = bhv * im_h;

    float4* bo = (float4*)(bbox + ((size_t)b * NLOC + loc) * 4);
    *bo = make_float4(cx, cy, bw2, bh2);

    float X1 = cx - bw2 * 0.5f, Y1 = cy - bh2 * 0.5f;
    float X2 = cx + bw2 * 0.5f, Y2 = cy + bh2 * 0.5f;
    int gi = b * NLOC + loc;
    g_x1[gi] = X1; g_y1[gi] = Y1;
    g_x2[gi] = X2; g_y2[gi] = Y2;
    g_ka[gi] = K2 * ((X2 - X1) * (Y2 - Y1));
    g_score[gi] = (obj < PRE_TH) ? 0.0f : obj;
}

// ============ kernel 2: per-batch bitonic sort ============
__global__ void __launch_bounds__(1024, 1)
sort_kernel()
{
    __shared__ float skey[NPAD];
    __shared__ int sidx[NPAD];
    const int b = blockIdx.x;
    const int tid = threadIdx.x;
    const int base = b * NLOC;

    for (int p = tid; p < NLOC; p += 1024) {
        skey[p] = g_score[base + p];
        sidx[p] = p;
    }
    for (int p = NLOC + tid; p < NPAD; p += 1024) {
        skey[p] = -1.0f;
        sidx[p] = NPAD + p;
    }
    __syncthreads();

    for (unsigned k = 2; k <= NPAD; k <<= 1) {
        for (unsigned j = k >> 1; j > 0; j >>= 1) {
            for (unsigned i = tid; i < NPAD; i += 1024) {
                unsigned ixj = i ^ j;
                if (ixj > i) {
                    float ka = skey[i], kb = skey[ixj];
                    int ia = sidx[i], ib = sidx[ixj];
                    bool b_before_a = (kb > ka) || (kb == ka && ib < ia);
                    bool dirDesc = ((i & k) == 0);
                    if (b_before_a == dirDesc) {
                        skey[i] = kb; skey[ixj] = ka;
                        sidx[i] = ib; sidx[ixj] = ia;
                    }
                }
            }
            __syncthreads();
        }
    }

    for (int p = tid; p < NLOC; p += 1024) {
        int o = sidx[p];
        float sc = skey[p];
        g_ss[base + p] = sc;
        g_sidx[base + p] = o;
        g_sbox[base + p] = make_float4(g_x1[base + o], g_y1[base + o],
                                       g_x2[base + o], g_y2[base + o]);
        // dead boxes can never suppress: ka = +INF makes inter > kai+kaj false
        g_ska[base + p] = (sc > 0.0f) ? g_ka[base + o] : INFINITY;
    }
    __syncthreads();
    for (int chunk = 0; chunk < NPAD; chunk += 1024) {
        int p = chunk + tid;
        bool alive = (p < NLOC) && (skey[p] > 0.0f);
        unsigned w = __ballot_sync(0xFFFFFFFFu, alive);
        int word = p >> 5;
        if ((tid & 31) == 0 && word < NW)
            g_alive[b * NW + word] = w;
    }
}

// ============ kernel 3: suppression matrix, column-major with coalesced stores ==
// warp owns (i-word w, j-word jword); 32 ballots accumulated, one 128B store.
__global__ void __launch_bounds__(128, 8)
mat_kernel()
{
    const int w = blockIdx.x;                       // i-word
    const int b = blockIdx.z;
    const int lane = threadIdx.x & 31;
    const int warpid = threadIdx.x >> 5;
    const int jword = blockIdx.y * 4 + warpid;      // j-word
    if (jword < w || jword >= NW) return;

    const int base = b * NLOC;
    const int i = w * 32 + lane;
    float4 ibx = make_float4(0.f, 0.f, 0.f, 0.f);
    float ika = INFINITY;
    if (i < NLOC) { ibx = g_sbox[base + i]; ika = g_ska[base + i]; }

    unsigned myword = 0u;
    const int jbase = jword * 32;

#pragma unroll 4
    for (int r = 0; r < 32; r++) {
        int j = jbase + r;
        if (j >= NLOC) break;                        // uniform
        float4 jb = __ldg(&g_sbox[base + j]);
        float jka = __ldg(&g_ska[base + j]);
        float iw = fminf(ibx.z, jb.z) - fmaxf(ibx.x, jb.x);
        float ih = fminf(ibx.w, jb.w) - fmaxf(ibx.y, jb.y);
        float inter = fmaxf(iw, 0.0f) * fmaxf(ih, 0.0f);
        bool sup = (inter > ika + jka) && (j > i);
        unsigned m = __ballot_sync(0xFFFFFFFFu, sup);
        if (lane == r) myword = m;
    }

    g_matC[((size_t)(b * NW + w)) * NLOCP + jbase + lane] = myword;
}

// ============ kernel 4: serial-column greedy sweep (exactly NW steps) ============
__global__ void __launch_bounds__(1024, 1)
reduce_kernel(float* __restrict__ out)
{
    __shared__ unsigned removed[NW];
    __shared__ unsigned keptw[NW];
    __shared__ unsigned kwShared;

    const int b = blockIdx.x;
    const int tid = threadIdx.x;
    const int base = b * NLOC;
    const unsigned* M = g_matC + (size_t)b * NW * NLOCP;

    for (int w = tid; w < NW; w += 1024) {
        removed[w] = ~g_alive[b * NW + w];   // dead boxes start removed
        keptw[w] = 0u;
    }
    __syncthreads();

    // ownership: rows j = tid + k*1024
    int jj[4]; int wj[4]; bool act[4];
    unsigned cur[4], nxt[4];
#pragma unroll
    for (int k = 0; k < 4; k++) {
        int j = tid + k * 1024;
        jj[k] = j;
        wj[k] = j >> 5;
        bool valid = (j < NLOC);
        bool alive = valid && !((removed[j >> 5] >> (j & 31)) & 1u);
        act[k] = alive && (wj[k] > 0);
        cur[k] = (act[k]) ? __ldg(M + j) : 0u;                        // word 0
        nxt[k] = (act[k] && wj[k] > 1) ? __ldg(M + NLOCP + j) : 0u;   // word 1
    }

    // warp0 diag preload for c=0: row r (r>0), word 0
    unsigned diag = 0u;
    if (tid < 32) {
        if (tid > 0) diag = __ldg(M + tid);
    }
    __syncthreads();

    for (int c = 0; c < NW; c++) {
        if (tid < 32) {
            unsigned cand = ~removed[c];
            unsigned kw = 0u;
            while (cand) {
                int b0 = __ffs(cand) - 1;
                kw |= 1u << b0;
                unsigned supBy = __ballot_sync(0xFFFFFFFFu, (diag >> b0) & 1u);
                cand &= ~supBy;
                cand &= ~(1u << b0);
            }
            if (tid == 0) { kwShared = kw; keptw[c] = kw; }
            // prefetch diag for c+1
            int cn = c + 1;
            unsigned nd = 0u;
            if (cn < NW) {
                int jn = cn * 32 + tid;
                if (tid > 0 && jn < NLOC)
                    nd = __ldg(M + (size_t)cn * NLOCP + jn);
            }
            diag = nd;
        }
        __syncthreads();                     // kwShared visible
        const unsigned kw = kwShared;

#pragma unroll
        for (int k = 0; k < 4; k++) {
            if (!act[k]) continue;
            // cur holds word c of row jj[k]; applies while wj > c
            if (cur[k] & kw) {
                atomicOr(&removed[wj[k]], 1u << (jj[k] & 31));
                act[k] = false;
                continue;
            }
            cur[k] = nxt[k];
            if (wj[k] <= c + 1) { act[k] = false; continue; }  // done applying
            // prefetch word c+2 (needed at iteration c+2 iff wj > c+2)
            nxt[k] = (wj[k] > c + 2) ? __ldg(M + (size_t)(c + 2) * NLOCP + jj[k]) : 0u;
        }
        __syncthreads();                     // removals visible; kwShared reusable
    }

    // scatter surviving scores into prob channel 20
    float* prob = out;
    for (int p = tid; p < NLOC; p += 1024) {
        int o = g_sidx[base + p];
        float sc = g_ss[base + p];
        float v = (((keptw[p >> 5] >> (p & 31)) & 1u)) ? sc : 0.0f;
        prob[((size_t)b * NLOC + o) * 21 + 20] = v;
    }
}

extern "C" void kernel_launch(void* const* d_in, const int* in_sizes, int n_in,
                              void* d_out, int out_size)
{
    (void)in_sizes; (void)n_in; (void)out_size;
    const float* x = (const float*)d_in[0];
    const float* im = (const float*)d_in[1];
    float* out = (float*)d_out;

    dim3 g1((NLOC + 127) / 128, BATCH);
    decode_kernel<<<g1, 128>>>(x, im, out);
    sort_kernel<<<BATCH, 1024>>>();
    dim3 g3(NW, (NW + 3) / 4, BATCH);
    mat_kernel<<<g3, 128>>>();
    reduce_kernel<<<BATCH, 1024>>>(out);
}

// round 6
// speedup vs baseline: 1.4382x; 1.4382x over previous
#include <cuda_runtime.h>
#include <math.h>

#define NCLS 20
#define NA 5
#define HH 26
#define WW 26
#define NLOC 3380      // NA*HH*WW
#define NLOCP 3392     // padded stride for matC
#define NPAD 4096
#define NW 106         // ceil(NLOC/32)
#define BATCH 16
#define NMS_TH 0.45f
#define K2 0.31034482758f   // 0.45/1.45
#define PRE_TH 0.005f
#define FEAT_STRIDE 32.0f

__constant__ float c_biases[10] = {1.08f, 1.19f, 3.42f, 4.41f, 6.63f, 11.38f,
                                   9.42f, 5.11f, 16.62f, 10.52f};

// ---- device scratch (static; no allocations) ----
__device__ float g_x1[BATCH * NLOC], g_y1[BATCH * NLOC];
__device__ float g_x2[BATCH * NLOC], g_y2[BATCH * NLOC];
__device__ float g_ka[BATCH * NLOC], g_score[BATCH * NLOC];
__device__ float4 g_sbox[BATCH * NLOC];          // sorted (x1,y1,x2,y2)
__device__ float g_ska[BATCH * NLOC], g_ss[BATCH * NLOC];
__device__ int g_sidx[BATCH * NLOC];
__device__ unsigned g_alive[BATCH * NW];
// column-major suppression matrix: matC[b][w][j] = i-word w suppressor bits of row j
__device__ unsigned g_matC[(size_t)BATCH * NW * NLOCP];   // ~23 MB

// ============ kernel 1: decode (fully parallel) ============
__global__ void decode_kernel(const float* __restrict__ x,
                              const float* __restrict__ im_info,
                              float* __restrict__ out)
{
    const int b = blockIdx.y;
    const int loc = blockIdx.x * 128 + threadIdx.x;
    if (loc >= NLOC) return;

    const float im_h = im_info[0];
    const float im_w = im_info[1];
    const float netw = WW * FEAT_STRIDE;
    const float neth = HH * FEAT_STRIDE;
    const bool cond = (netw / im_w) < (neth / im_h);
    const float new_w = cond ? netw : im_w * neth / im_h;
    const float new_h = cond ? im_h * netw / im_w : neth;

    float* prob = out;
    float* bbox = out + (size_t)BATCH * NLOC * 21;
    const float* xb = x + (size_t)b * 125 * (HH * WW);

    int a = loc / (HH * WW);
    int rem = loc - a * (HH * WW);
    int hh = rem / WW;
    int ww = rem - hh * WW;

    float tx = xb[(2 * a) * 676 + rem];
    float ty = xb[(2 * a + 1) * 676 + rem];
    float tw = xb[(10 + 2 * a) * 676 + rem];
    float th = xb[(11 + 2 * a) * 676 + rem];
    float to = xb[(20 + a) * 676 + rem];

    float obj = 1.0f / (1.0f + expf(-to));

    float cf[NCLS];
    float m = -INFINITY;
#pragma unroll
    for (int c = 0; c < NCLS; c++) {
        cf[c] = xb[(25 + 5 * c + a) * 676 + rem];
        m = fmaxf(m, cf[c]);
    }
    float sum = 0.0f;
#pragma unroll
    for (int c = 0; c < NCLS; c++) {
        cf[c] = expf(cf[c] - m);
        sum += cf[c];
    }
    float inv = obj / sum;
    float* pr = prob + ((size_t)b * NLOC + loc) * 21;
#pragma unroll
    for (int c = 0; c < NCLS; c++) pr[c] = cf[c] * inv;

    float sx = 1.0f / (1.0f + expf(-tx));
    float sy = 1.0f / (1.0f + expf(-ty));
    float bxv = ((float)ww + sx) / (float)WW;
    float byv = ((float)hh + sy) / (float)HH;
    float bwv = c_biases[2 * a] * expf(tw) / (float)WW;
    float bhv = c_biases[2 * a + 1] * expf(th) / (float)HH;

    bxv = (bxv - (netw - new_w) * 0.5f / netw) / (new_w / netw);
    byv = (byv - (neth - new_h) * 0.5f / neth) / (new_h / neth);
    bwv = bwv * (netw / new_w);
    bhv = bhv * (neth / new_h);

    float cx = bxv * im_w, cy = byv * im_h;
    float bw2 = bwv * im_w, bh2 = bhv * im_h;

    float4* bo = (float4*)(bbox + ((size_t)b * NLOC + loc) * 4);
    *bo = make_float4(cx, cy, bw2, bh2);

    float X1 = cx - bw2 * 0.5f, Y1 = cy - bh2 * 0.5f;
    float X2 = cx + bw2 * 0.5f, Y2 = cy + bh2 * 0.5f;
    int gi = b * NLOC + loc;
    g_x1[gi] = X1; g_y1[gi] = Y1;
    g_x2[gi] = X2; g_y2[gi] = Y2;
    g_ka[gi] = K2 * ((X2 - X1) * (Y2 - Y1));
    g_score[gi] = (obj < PRE_TH) ? 0.0f : obj;
}

// ============ kernel 2: per-batch bitonic sort ============
__global__ void __launch_bounds__(1024, 1)
sort_kernel()
{
    __shared__ float skey[NPAD];
    __shared__ int sidx[NPAD];
    const int b = blockIdx.x;
    const int tid = threadIdx.x;
    const int base = b * NLOC;

    for (int p = tid; p < NLOC; p += 1024) {
        skey[p] = g_score[base + p];
        sidx[p] = p;
    }
    for (int p = NLOC + tid; p < NPAD; p += 1024) {
        skey[p] = -1.0f;
        sidx[p] = NPAD + p;
    }
    __syncthreads();

    for (unsigned k = 2; k <= NPAD; k <<= 1) {
        for (unsigned j = k >> 1; j > 0; j >>= 1) {
            for (unsigned i = tid; i < NPAD; i += 1024) {
                unsigned ixj = i ^ j;
                if (ixj > i) {
                    float ka = skey[i], kb = skey[ixj];
                    int ia = sidx[i], ib = sidx[ixj];
                    bool b_before_a = (kb > ka) || (kb == ka && ib < ia);
                    bool dirDesc = ((i & k) == 0);
                    if (b_before_a == dirDesc) {
                        skey[i] = kb; skey[ixj] = ka;
                        sidx[i] = ib; sidx[ixj] = ia;
                    }
                }
            }
            __syncthreads();
        }
    }

    for (int p = tid; p < NLOC; p += 1024) {
        int o = sidx[p];
        float sc = skey[p];
        g_ss[base + p] = sc;
        g_sidx[base + p] = o;
        g_sbox[base + p] = make_float4(g_x1[base + o], g_y1[base + o],
                                       g_x2[base + o], g_y2[base + o]);
        // dead boxes can never suppress: ka = +INF makes inter > kai+kaj false
        g_ska[base + p] = (sc > 0.0f) ? g_ka[base + o] : INFINITY;
    }
    __syncthreads();
    for (int chunk = 0; chunk < NPAD; chunk += 1024) {
        int p = chunk + tid;
        bool alive = (p < NLOC) && (skey[p] > 0.0f);
        unsigned w = __ballot_sync(0xFFFFFFFFu, alive);
        int word = p >> 5;
        if ((tid & 31) == 0 && word < NW)
            g_alive[b * NW + word] = w;
    }
}

// ============ kernel 3: suppression matrix, column-major, coalesced stores ======
__global__ void __launch_bounds__(128, 8)
mat_kernel()
{
    const int w = blockIdx.x;                       // i-word
    const int b = blockIdx.z;
    const int lane = threadIdx.x & 31;
    const int warpid = threadIdx.x >> 5;
    const int jword = blockIdx.y * 4 + warpid;      // j-word
    if (jword < w || jword >= NW) return;

    const int base = b * NLOC;
    const int i = w * 32 + lane;
    float4 ibx = make_float4(0.f, 0.f, 0.f, 0.f);
    float ika = INFINITY;
    if (i < NLOC) { ibx = g_sbox[base + i]; ika = g_ska[base + i]; }

    unsigned myword = 0u;
    const int jbase = jword * 32;

#pragma unroll 4
    for (int r = 0; r < 32; r++) {
        int j = jbase + r;
        if (j >= NLOC) break;                        // uniform
        float4 jb = __ldg(&g_sbox[base + j]);
        float jka = __ldg(&g_ska[base + j]);
        float iw = fminf(ibx.z, jb.z) - fmaxf(ibx.x, jb.x);
        float ih = fminf(ibx.w, jb.w) - fmaxf(ibx.y, jb.y);
        float inter = fmaxf(iw, 0.0f) * fmaxf(ih, 0.0f);
        bool sup = (inter > ika + jka) && (j > i);
        unsigned m = __ballot_sync(0xFFFFFFFFu, sup);
        if (lane == r) myword = m;
    }

    g_matC[((size_t)(b * NW + w)) * NLOCP + jbase + lane] = myword;
}

// ============ kernel 4: cursor fixpoint reduction (coalesced, column-major) =====
__global__ void __launch_bounds__(1024, 1)
reduce_kernel(float* __restrict__ out)
{
    __shared__ unsigned kept[NW];
    __shared__ unsigned removed[NW];
    __shared__ int changed;

    const int b = blockIdx.x;
    const int tid = threadIdx.x;
    const int base = b * NLOC;
    const unsigned* M = g_matC + (size_t)b * NW * NLOCP;   // M[w*NLOCP + j]

    for (int w = tid; w < NW; w += 1024) {
        kept[w] = 0u;
        removed[w] = ~g_alive[b * NW + w];   // dead boxes start removed
    }
    __syncthreads();

    bool det[4];
    int cw[4];
    unsigned cache[4];

    // ---- init: find first stall word per j (kept==0 now; only removed matters)
#pragma unroll
    for (int k = 0; k < 4; k++) {
        int j = tid + k * 1024;
        det[k] = true;
        cw[k] = 0; cache[k] = 0u;
        if (j >= NLOC) continue;
        if ((removed[j >> 5] >> (j & 31)) & 1u) continue;     // dead -> done
        int nwj = (j == 0) ? 0 : (((j - 1) >> 5) + 1);
        int stall = -1;
        unsigned sraw = 0u;
        for (int c0 = 0; c0 < nwj && stall < 0; c0 += 16) {
            unsigned vbuf[16];
#pragma unroll
            for (int t = 0; t < 16; t++) {
                int wi = c0 + t;
                vbuf[t] = (wi < nwj) ? __ldg(M + (size_t)wi * NLOCP + j) : 0u;
            }
#pragma unroll
            for (int t = 0; t < 16; t++) {
                int wi = c0 + t;
                if (stall < 0 && wi < nwj) {
                    unsigned live = vbuf[t] & ~removed[wi];
                    if (live) { stall = wi; sraw = vbuf[t]; }
                }
            }
        }
        if (stall < 0) {
            atomicOr(&kept[j >> 5], 1u << (j & 31));          // no live suppressors
        } else {
            det[k] = false; cw[k] = stall; cache[k] = sraw;
        }
    }
    __syncthreads();

    // ---- rounds
    while (true) {
        if (tid == 0) changed = 0;
        __syncthreads();

#pragma unroll
        for (int k = 0; k < 4; k++) {
            if (det[k]) continue;
            int j = tid + k * 1024;
            int nwj = ((j - 1) >> 5) + 1;                     // j >= 1 here

            unsigned raw = cache[k];
            int w = cw[k];
            if (raw & kept[w]) {
                atomicOr(&removed[j >> 5], 1u << (j & 31));
                det[k] = true; changed = 1;
                continue;
            }
            if (raw & ~removed[w]) continue;                  // still stalled

            // stall word cleared: advance
            int stall = -1; unsigned sraw = 0u; bool rem = false;
            for (int c0 = w + 1; c0 < nwj && stall < 0 && !rem; c0 += 8) {
                unsigned vbuf[8];
#pragma unroll
                for (int t = 0; t < 8; t++) {
                    int wi = c0 + t;
                    vbuf[t] = (wi < nwj) ? __ldg(M + (size_t)wi * NLOCP + j) : 0u;
                }
#pragma unroll
                for (int t = 0; t < 8; t++) {
                    int wi = c0 + t;
                    if (stall < 0 && !rem && wi < nwj && vbuf[t]) {
                        if (vbuf[t] & kept[wi]) { rem = true; }
                        else if (vbuf[t] & ~removed[wi]) { stall = wi; sraw = vbuf[t]; }
                    }
                }
            }
            if (rem) {
                atomicOr(&removed[j >> 5], 1u << (j & 31));
                det[k] = true; changed = 1;
            } else if (stall < 0) {
                atomicOr(&kept[j >> 5], 1u << (j & 31));
                det[k] = true; changed = 1;
            } else {
                cw[k] = stall; cache[k] = sraw; changed = 1;  // made progress
            }
        }
        __syncthreads();
        if (!changed) break;
        __syncthreads();
    }

    // ---- scatter surviving scores into prob channel 20
    float* prob = out;
    for (int p = tid; p < NLOC; p += 1024) {
        int o = g_sidx[base + p];
        float sc = g_ss[base + p];
        float v = (sc > 0.0f && ((kept[p >> 5] >> (p & 31)) & 1u)) ? sc : 0.0f;
        prob[((size_t)b * NLOC + o) * 21 + 20] = v;
    }
}

extern "C" void kernel_launch(void* const* d_in, const int* in_sizes, int n_in,
                              void* d_out, int out_size)
{
    (void)in_sizes; (void)n_in; (void)out_size;
    const float* x = (const float*)d_in[0];
    const float* im = (const float*)d_in[1];
    float* out = (float*)d_out;

    dim3 g1((NLOC + 127) / 128, BATCH);
    decode_kernel<<<g1, 128>>>(x, im, out);
    sort_kernel<<<BATCH, 1024>>>();
    dim3 g3(NW, (NW + 3) / 4, BATCH);
    mat_kernel<<<g3, 128>>>();
    reduce_kernel<<<BATCH, 1024>>>(out);
}

// round 7
// speedup vs baseline: 1.4844x; 1.0321x over previous
#include <cuda_runtime.h>
#include <math.h>

#define NCLS 20
#define NA 5
#define HH 26
#define WW 26
#define NLOC 3380      // NA*HH*WW
#define NLOCP 3392     // padded stride for matC
#define NPAD 4096
#define NW 106         // ceil(NLOC/32)
#define BATCH 16
#define NMS_TH 0.45f
#define K2 0.31034482758f   // 0.45/1.45
#define PRE_TH 0.005f
#define FEAT_STRIDE 32.0f

__constant__ float c_biases[10] = {1.08f, 1.19f, 3.42f, 4.41f, 6.63f, 11.38f,
                                   9.42f, 5.11f, 16.62f, 10.52f};

// ---- device scratch (static; no allocations) ----
__device__ float g_x1[BATCH * NLOC], g_y1[BATCH * NLOC];
__device__ float g_x2[BATCH * NLOC], g_y2[BATCH * NLOC];
__device__ float g_ka[BATCH * NLOC], g_score[BATCH * NLOC];
__device__ float4 g_sbox[BATCH * NLOC];          // sorted (x1,y1,x2,y2)
__device__ float g_ska[BATCH * NLOC], g_ss[BATCH * NLOC];
__device__ int g_sidx[BATCH * NLOC];
__device__ unsigned g_alive[BATCH * NW];
// column-major suppression matrix: matC[b][w][j] = i-word w suppressor bits of row j
__device__ unsigned g_matC[(size_t)BATCH * NW * NLOCP];   // ~23 MB

// ============ kernel 1: decode (fully parallel) ============
__global__ void decode_kernel(const float* __restrict__ x,
                              const float* __restrict__ im_info,
                              float* __restrict__ out)
{
    const int b = blockIdx.y;
    const int loc = blockIdx.x * 128 + threadIdx.x;
    if (loc >= NLOC) return;

    const float im_h = im_info[0];
    const float im_w = im_info[1];
    const float netw = WW * FEAT_STRIDE;
    const float neth = HH * FEAT_STRIDE;
    const bool cond = (netw / im_w) < (neth / im_h);
    const float new_w = cond ? netw : im_w * neth / im_h;
    const float new_h = cond ? im_h * netw / im_w : neth;

    float* prob = out;
    float* bbox = out + (size_t)BATCH * NLOC * 21;
    const float* xb = x + (size_t)b * 125 * (HH * WW);

    int a = loc / (HH * WW);
    int rem = loc - a * (HH * WW);
    int hh = rem / WW;
    int ww = rem - hh * WW;

    float tx = xb[(2 * a) * 676 + rem];
    float ty = xb[(2 * a + 1) * 676 + rem];
    float tw = xb[(10 + 2 * a) * 676 + rem];
    float th = xb[(11 + 2 * a) * 676 + rem];
    float to = xb[(20 + a) * 676 + rem];

    float obj = 1.0f / (1.0f + expf(-to));

    float cf[NCLS];
    float m = -INFINITY;
#pragma unroll
    for (int c = 0; c < NCLS; c++) {
        cf[c] = xb[(25 + 5 * c + a) * 676 + rem];
        m = fmaxf(m, cf[c]);
    }
    float sum = 0.0f;
#pragma unroll
    for (int c = 0; c < NCLS; c++) {
        cf[c] = expf(cf[c] - m);
        sum += cf[c];
    }
    float inv = obj / sum;
    float* pr = prob + ((size_t)b * NLOC + loc) * 21;
#pragma unroll
    for (int c = 0; c < NCLS; c++) pr[c] = cf[c] * inv;

    float sx = 1.0f / (1.0f + expf(-tx));
    float sy = 1.0f / (1.0f + expf(-ty));
    float bxv = ((float)ww + sx) / (float)WW;
    float byv = ((float)hh + sy) / (float)HH;
    float bwv = c_biases[2 * a] * expf(tw) / (float)WW;
    float bhv = c_biases[2 * a + 1] * expf(th) / (float)HH;

    bxv = (bxv - (netw - new_w) * 0.5f / netw) / (new_w / netw);
    byv = (byv - (neth - new_h) * 0.5f / neth) / (new_h / neth);
    bwv = bwv * (netw / new_w);
    bhv = bhv * (neth / new_h);

    float cx = bxv * im_w, cy = byv * im_h;
    float bw2 = bwv * im_w, bh2 = bhv * im_h;

    float4* bo = (float4*)(bbox + ((size_t)b * NLOC + loc) * 4);
    *bo = make_float4(cx, cy, bw2, bh2);

    float X1 = cx - bw2 * 0.5f, Y1 = cy - bh2 * 0.5f;
    float X2 = cx + bw2 * 0.5f, Y2 = cy + bh2 * 0.5f;
    int gi = b * NLOC + loc;
    g_x1[gi] = X1; g_y1[gi] = Y1;
    g_x2[gi] = X2; g_y2[gi] = Y2;
    g_ka[gi] = K2 * ((X2 - X1) * (Y2 - Y1));
    g_score[gi] = (obj < PRE_TH) ? 0.0f : obj;
}

// ============ kernel 2: per-batch bitonic sort on packed 64-bit keys ============
// key = (float_bits(score) << 32) | (0xFFFFFFFF - idx)
// uint64 descending == (score desc, idx asc); keys unique; padding = 0 sorts last.
__global__ void __launch_bounds__(1024, 1)
sort_kernel()
{
    __shared__ unsigned long long skey[NPAD];
    const int b = blockIdx.x;
    const int tid = threadIdx.x;
    const int base = b * NLOC;

    for (int p = tid; p < NLOC; p += 1024) {
        unsigned sb = __float_as_uint(g_score[base + p]);
        skey[p] = ((unsigned long long)sb << 32) | (0xFFFFFFFFu - (unsigned)p);
    }
    for (int p = NLOC + tid; p < NPAD; p += 1024)
        skey[p] = 0ull;
    __syncthreads();

    for (unsigned k = 2; k <= NPAD; k <<= 1) {
        for (unsigned j = k >> 1; j > 0; j >>= 1) {
            for (unsigned i = tid; i < NPAD; i += 1024) {
                unsigned ixj = i ^ j;
                if (ixj > i) {
                    unsigned long long ka = skey[i], kb = skey[ixj];
                    bool dirDesc = ((i & k) == 0);
                    if ((kb > ka) == dirDesc) {
                        skey[i] = kb;
                        skey[ixj] = ka;
                    }
                }
            }
            __syncthreads();
        }
    }

    for (int p = tid; p < NLOC; p += 1024) {
        unsigned long long key = skey[p];
        float sc = __uint_as_float((unsigned)(key >> 32));
        int o = (int)(0xFFFFFFFFu - (unsigned)key);
        g_ss[base + p] = sc;
        g_sidx[base + p] = o;
        g_sbox[base + p] = make_float4(g_x1[base + o], g_y1[base + o],
                                       g_x2[base + o], g_y2[base + o]);
        // dead boxes can never suppress: ka = +INF makes inter > kai+kaj false
        g_ska[base + p] = (sc > 0.0f) ? g_ka[base + o] : INFINITY;
    }
    __syncthreads();
    for (int chunk = 0; chunk < NPAD; chunk += 1024) {
        int p = chunk + tid;
        bool alive = (p < NLOC) && ((skey[p] >> 32) != 0ull);
        unsigned w = __ballot_sync(0xFFFFFFFFu, alive);
        int word = p >> 5;
        if ((tid & 31) == 0 && word < NW)
            g_alive[b * NW + word] = w;
    }
}

// ============ kernel 3: suppression matrix, column-major, coalesced stores ======
__global__ void __launch_bounds__(128, 8)
mat_kernel()
{
    const int w = blockIdx.x;                       // i-word
    const int b = blockIdx.z;
    const int lane = threadIdx.x & 31;
    const int warpid = threadIdx.x >> 5;
    const int jword = blockIdx.y * 4 + warpid;      // j-word
    if (jword < w || jword >= NW) return;

    const int base = b * NLOC;
    const int i = w * 32 + lane;
    float4 ibx = make_float4(0.f, 0.f, 0.f, 0.f);
    float ika = INFINITY;
    if (i < NLOC) { ibx = g_sbox[base + i]; ika = g_ska[base + i]; }

    unsigned myword = 0u;
    const int jbase = jword * 32;

#pragma unroll 4
    for (int r = 0; r < 32; r++) {
        int j = jbase + r;
        if (j >= NLOC) break;                        // uniform
        float4 jb = __ldg(&g_sbox[base + j]);
        float jka = __ldg(&g_ska[base + j]);
        float iw = fminf(ibx.z, jb.z) - fmaxf(ibx.x, jb.x);
        float ih = fminf(ibx.w, jb.w) - fmaxf(ibx.y, jb.y);
        float inter = fmaxf(iw, 0.0f) * fmaxf(ih, 0.0f);
        bool sup = (inter > ika + jka) && (j > i);
        unsigned m = __ballot_sync(0xFFFFFFFFu, sup);
        if (lane == r) myword = m;
    }

    g_matC[((size_t)(b * NW + w)) * NLOCP + jbase + lane] = myword;
}

// ============ kernel 4: monotone fixpoint, single barrier per round ============
__global__ void __launch_bounds__(1024, 1)
reduce_kernel(float* __restrict__ out)
{
    __shared__ unsigned kept[NW];
    __shared__ unsigned removed[NW];
    __shared__ int chg[3];

    const int b = blockIdx.x;
    const int tid = threadIdx.x;
    const int base = b * NLOC;
    const unsigned* M = g_matC + (size_t)b * NW * NLOCP;   // M[w*NLOCP + j]

    for (int w = tid; w < NW; w += 1024) {
        kept[w] = 0u;
        removed[w] = ~g_alive[b * NW + w];   // dead boxes start removed
    }
    if (tid < 3) chg[tid] = 0;
    __syncthreads();

    bool det[4];
    int cw[4];
    unsigned cache[4];

    // ---- init: find first stall word per j (kept==0 now; only removed matters)
#pragma unroll
    for (int k = 0; k < 4; k++) {
        int j = tid + k * 1024;
        det[k] = true;
        cw[k] = 0; cache[k] = 0u;
        if (j >= NLOC) continue;
        if ((removed[j >> 5] >> (j & 31)) & 1u) continue;     // dead -> done
        int nwj = (j == 0) ? 0 : (((j - 1) >> 5) + 1);
        int stall = -1;
        unsigned sraw = 0u;
        for (int c0 = 0; c0 < nwj && stall < 0; c0 += 16) {
            unsigned vbuf[16];
#pragma unroll
            for (int t = 0; t < 16; t++) {
                int wi = c0 + t;
                vbuf[t] = (wi < nwj) ? __ldg(M + (size_t)wi * NLOCP + j) : 0u;
            }
#pragma unroll
            for (int t = 0; t < 16; t++) {
                int wi = c0 + t;
                if (stall < 0 && wi < nwj) {
                    unsigned live = vbuf[t] & ~removed[wi];
                    if (live) { stall = wi; sraw = vbuf[t]; }
                }
            }
        }
        if (stall < 0) {
            atomicOr(&kept[j >> 5], 1u << (j & 31));          // no live suppressors
        } else {
            det[k] = false; cw[k] = stall; cache[k] = sraw;
        }
    }
    __syncthreads();

    // ---- rounds: monotone lattice -> stale reads safe; ONE barrier per round.
    // chg 3-slot rotation: round r writes slot r%3; thread0 clears slot (r+1)%3
    // before the barrier (nobody writes it until round r+1); all read r%3 after.
    int r = 0;
    while (true) {
        const int slot = r - (r / 3) * 3;
        int next = slot + 1; if (next == 3) next = 0;

#pragma unroll
        for (int k = 0; k < 4; k++) {
            if (det[k]) continue;
            int j = tid + k * 1024;
            int nwj = ((j - 1) >> 5) + 1;                     // j >= 1 here

            unsigned raw = cache[k];
            int w = cw[k];
            if (raw & kept[w]) {
                atomicOr(&removed[j >> 5], 1u << (j & 31));
                det[k] = true; chg[slot] = 1;
                continue;
            }
            if (raw & ~removed[w]) continue;                  // still stalled

            // stall word cleared: advance
            int stall = -1; unsigned sraw = 0u; bool rem = false;
            for (int c0 = w + 1; c0 < nwj && stall < 0 && !rem; c0 += 8) {
                unsigned vbuf[8];
#pragma unroll
                for (int t = 0; t < 8; t++) {
                    int wi = c0 + t;
                    vbuf[t] = (wi < nwj) ? __ldg(M + (size_t)wi * NLOCP + j) : 0u;
                }
#pragma unroll
                for (int t = 0; t < 8; t++) {
                    int wi = c0 + t;
                    if (stall < 0 && !rem && wi < nwj && vbuf[t]) {
                        if (vbuf[t] & kept[wi]) { rem = true; }
                        else if (vbuf[t] & ~removed[wi]) { stall = wi; sraw = vbuf[t]; }
                    }
                }
            }
            if (rem) {
                atomicOr(&removed[j >> 5], 1u << (j & 31));
                det[k] = true; chg[slot] = 1;
            } else if (stall < 0) {
                atomicOr(&kept[j >> 5], 1u << (j & 31));
                det[k] = true; chg[slot] = 1;
            } else {
                cw[k] = stall; cache[k] = sraw; chg[slot] = 1; // made progress
            }
        }
        if (tid == 0) chg[next] = 0;
        __syncthreads();
        if (!chg[slot]) break;
        r++;
    }

    // ---- scatter surviving scores into prob channel 20
    float* prob = out;
    for (int p = tid; p < NLOC; p += 1024) {
        int o = g_sidx[base + p];
        float sc = g_ss[base + p];
        float v = (sc > 0.0f && ((kept[p >> 5] >> (p & 31)) & 1u)) ? sc : 0.0f;
        prob[((size_t)b * NLOC + o) * 21 + 20] = v;
    }
}

extern "C" void kernel_launch(void* const* d_in, const int* in_sizes, int n_in,
                              void* d_out, int out_size)
{
    (void)in_sizes; (void)n_in; (void)out_size;
    const float* x = (const float*)d_in[0];
    const float* im = (const float*)d_in[1];
    float* out = (float*)d_out;

    dim3 g1((NLOC + 127) / 128, BATCH);
    decode_kernel<<<g1, 128>>>(x, im, out);
    sort_kernel<<<BATCH, 1024>>>();
    dim3 g3(NW, (NW + 3) / 4, BATCH);
    mat_kernel<<<g3, 128>>>();
    reduce_kernel<<<BATCH, 1024>>>(out);
}

// round 9
// speedup vs baseline: 1.7155x; 1.1557x over previous
#include <cuda_runtime.h>
#include <math.h>

#define NCLS 20
#define NA 5
#define HH 26
#define WW 26
#define NLOC 3380      // NA*HH*WW
#define NLOCP 3392     // padded stride for matC
#define NPAD 4096
#define NW 106         // ceil(NLOC/32)
#define BATCH 16
#define NMS_TH 0.45f
#define K2 0.31034482758f   // 0.45/1.45
#define PRE_TH 0.005f
#define FEAT_STRIDE 32.0f

__constant__ float c_biases[10] = {1.08f, 1.19f, 3.42f, 4.41f, 6.63f, 11.38f,
                                   9.42f, 5.11f, 16.62f, 10.52f};

// ---- device scratch (static; no allocations) ----
__device__ float g_x1[BATCH * NLOC], g_y1[BATCH * NLOC];
__device__ float g_x2[BATCH * NLOC], g_y2[BATCH * NLOC];
__device__ float g_ka[BATCH * NLOC], g_score[BATCH * NLOC];
__device__ float4 g_sbox[BATCH * NLOC];          // sorted (x1,y1,x2,y2)
__device__ float g_ska[BATCH * NLOC], g_ss[BATCH * NLOC];
__device__ int g_sidx[BATCH * NLOC];
__device__ unsigned g_alive[BATCH * NW];
// column-major suppression matrix: matC[b][w][j] = i-word w suppressor bits of row j
__device__ unsigned g_matC[(size_t)BATCH * NW * NLOCP];   // ~23 MB
// per-row bitmap of NONZERO suppressor words (128 bits, words 0..105)
__device__ unsigned g_rowmask[(size_t)BATCH * NLOCP * 4];

// ============ kernel 1: decode (fully parallel) ============
__global__ void decode_kernel(const float* __restrict__ x,
                              const float* __restrict__ im_info,
                              float* __restrict__ out)
{
    const int b = blockIdx.y;
    const int loc = blockIdx.x * 128 + threadIdx.x;
    if (loc >= NLOC) return;

    // zero this batch's rowmask entry for rank==loc (replay-safe re-init)
    *((uint4*)&g_rowmask[((size_t)(b * NLOCP + loc)) * 4]) = make_uint4(0u, 0u, 0u, 0u);

    const float im_h = im_info[0];
    const float im_w = im_info[1];
    const float netw = WW * FEAT_STRIDE;
    const float neth = HH * FEAT_STRIDE;
    const bool cond = (netw / im_w) < (neth / im_h);
    const float new_w = cond ? netw : im_w * neth / im_h;
    const float new_h = cond ? im_h * netw / im_w : neth;

    float* prob = out;
    float* bbox = out + (size_t)BATCH * NLOC * 21;
    const float* xb = x + (size_t)b * 125 * (HH * WW);

    int a = loc / (HH * WW);
    int rem = loc - a * (HH * WW);
    int hh = rem / WW;
    int ww = rem - hh * WW;

    float tx = xb[(2 * a) * 676 + rem];
    float ty = xb[(2 * a + 1) * 676 + rem];
    float tw = xb[(10 + 2 * a) * 676 + rem];
    float th = xb[(11 + 2 * a) * 676 + rem];
    float to = xb[(20 + a) * 676 + rem];

    float obj = 1.0f / (1.0f + expf(-to));

    float cf[NCLS];
    float m = -INFINITY;
#pragma unroll
    for (int c = 0; c < NCLS; c++) {
        cf[c] = xb[(25 + 5 * c + a) * 676 + rem];
        m = fmaxf(m, cf[c]);
    }
    float sum = 0.0f;
#pragma unroll
    for (int c = 0; c < NCLS; c++) {
        cf[c] = expf(cf[c] - m);
        sum += cf[c];
    }
    float inv = obj / sum;
    float* pr = prob + ((size_t)b * NLOC + loc) * 21;
#pragma unroll
    for (int c = 0; c < NCLS; c++) pr[c] = cf[c] * inv;

    float sx = 1.0f / (1.0f + expf(-tx));
    float sy = 1.0f / (1.0f + expf(-ty));
    float bxv = ((float)ww + sx) / (float)WW;
    float byv = ((float)hh + sy) / (float)HH;
    float bwv = c_biases[2 * a] * expf(tw) / (float)WW;
    float bhv = c_biases[2 * a + 1] * expf(th) / (float)HH;

    bxv = (bxv - (netw - new_w) * 0.5f / netw) / (new_w / netw);
    byv = (byv - (neth - new_h) * 0.5f / neth) / (new_h / neth);
    bwv = bwv * (netw / new_w);
    bhv = bhv * (neth / new_h);

    float cx = bxv * im_w, cy = byv * im_h;
    float bw2 = bwv * im_w, bh2 = bhv * im_h;

    float4* bo = (float4*)(bbox + ((size_t)b * NLOC + loc) * 4);
    *bo = make_float4(cx, cy, bw2, bh2);

    float X1 = cx - bw2 * 0.5f, Y1 = cy - bh2 * 0.5f;
    float X2 = cx + bw2 * 0.5f, Y2 = cy + bh2 * 0.5f;
    int gi = b * NLOC + loc;
    g_x1[gi] = X1; g_y1[gi] = Y1;
    g_x2[gi] = X2; g_y2[gi] = Y2;
    g_ka[gi] = K2 * ((X2 - X1) * (Y2 - Y1));
    g_score[gi] = (obj < PRE_TH) ? 0.0f : obj;
}

// ============ kernel 2: per-batch bitonic sort on packed 64-bit keys ============
// key = (float_bits(score) << 32) | (0xFFFFFFFF - idx)
// uint64 descending == (score desc, idx asc); keys unique; padding = 0 sorts last.
__global__ void __launch_bounds__(1024, 1)
sort_kernel()
{
    __shared__ unsigned long long skey[NPAD];
    const int b = blockIdx.x;
    const int tid = threadIdx.x;
    const int base = b * NLOC;

    for (int p = tid; p < NLOC; p += 1024) {
        unsigned sb = __float_as_uint(g_score[base + p]);
        skey[p] = ((unsigned long long)sb << 32) | (0xFFFFFFFFu - (unsigned)p);
    }
    for (int p = NLOC + tid; p < NPAD; p += 1024)
        skey[p] = 0ull;
    __syncthreads();

    for (unsigned k = 2; k <= NPAD; k <<= 1) {
        for (unsigned j = k >> 1; j > 0; j >>= 1) {
            for (unsigned i = tid; i < NPAD; i += 1024) {
                unsigned ixj = i ^ j;
                if (ixj > i) {
                    unsigned long long ka = skey[i], kb = skey[ixj];
                    bool dirDesc = ((i & k) == 0);
                    if ((kb > ka) == dirDesc) {
                        skey[i] = kb;
                        skey[ixj] = ka;
                    }
                }
            }
            __syncthreads();
        }
    }

    for (int p = tid; p < NLOC; p += 1024) {
        unsigned long long key = skey[p];
        float sc = __uint_as_float((unsigned)(key >> 32));
        int o = (int)(0xFFFFFFFFu - (unsigned)key);
        g_ss[base + p] = sc;
        g_sidx[base + p] = o;
        g_sbox[base + p] = make_float4(g_x1[base + o], g_y1[base + o],
                                       g_x2[base + o], g_y2[base + o]);
        // dead boxes can never suppress: ka = +INF makes inter > kai+kaj false
        g_ska[base + p] = (sc > 0.0f) ? g_ka[base + o] : INFINITY;
    }
    __syncthreads();
    for (int chunk = 0; chunk < NPAD; chunk += 1024) {
        int p = chunk + tid;
        bool alive = (p < NLOC) && ((skey[p] >> 32) != 0ull);
        unsigned w = __ballot_sync(0xFFFFFFFFu, alive);
        int word = p >> 5;
        if ((tid & 31) == 0 && word < NW)
            g_alive[b * NW + word] = w;
    }
}

// ============ kernel 3: suppression matrix + per-row live-word bitmap ==========
__global__ void __launch_bounds__(128, 8)
mat_kernel()
{
    const int w = blockIdx.x;                       // i-word
    const int b = blockIdx.z;
    const int lane = threadIdx.x & 31;
    const int warpid = threadIdx.x >> 5;
    const int jword = blockIdx.y * 4 + warpid;      // j-word
    if (jword < w || jword >= NW) return;

    const int base = b * NLOC;
    const int i = w * 32 + lane;
    float4 ibx = make_float4(0.f, 0.f, 0.f, 0.f);
    float ika = INFINITY;
    if (i < NLOC) { ibx = g_sbox[base + i]; ika = g_ska[base + i]; }

    unsigned myword = 0u;
    const int jbase = jword * 32;

#pragma unroll 4
    for (int r = 0; r < 32; r++) {
        int j = jbase + r;
        if (j >= NLOC) break;                        // uniform
        float4 jb = __ldg(&g_sbox[base + j]);
        float jka = __ldg(&g_ska[base + j]);
        float iw = fminf(ibx.z, jb.z) - fmaxf(ibx.x, jb.x);
        float ih = fminf(ibx.w, jb.w) - fmaxf(ibx.y, jb.y);
        float inter = fmaxf(iw, 0.0f) * fmaxf(ih, 0.0f);
        bool sup = (inter > ika + jka) && (j > i);
        unsigned m = __ballot_sync(0xFFFFFFFFu, sup);
        if (lane == r) myword = m;
    }

    int j = jbase + lane;
    g_matC[((size_t)(b * NW + w)) * NLOCP + j] = myword;
    // record this word as live in row j's 128-bit mask (bits exclude dead i by
    // construction: dead ska=+INF never suppresses)
    if (myword && j < NLOC)
        atomicOr(&g_rowmask[((size_t)(b * NLOCP + j)) * 4 + (w >> 5)],
                 1u << (w & 31));
}

// ============ kernel 4: fixpoint on live-word bitmaps (no zero-scanning) =======
__global__ void __launch_bounds__(1024, 1)
reduce_kernel(float* __restrict__ out)
{
    __shared__ unsigned kept[NW];
    __shared__ unsigned removed[NW];
    __shared__ int chg[3];

    const int b = blockIdx.x;
    const int tid = threadIdx.x;
    const int base = b * NLOC;
    const unsigned* M = g_matC + (size_t)b * NW * NLOCP;   // M[w*NLOCP + j]

    for (int w = tid; w < NW; w += 1024) {
        kept[w] = 0u;
        removed[w] = ~g_alive[b * NW + w];   // dead boxes start removed
    }
    if (tid < 3) chg[tid] = 0;
    __syncthreads();

    bool det[4];
    int cw[4];
    unsigned cache[4];
    unsigned long long rmA[4], rmB[4];   // live-word bitmap: words 0..63 / 64..105

    // ---- init: cursor = first live word straight from the bitmap
#pragma unroll
    for (int k = 0; k < 4; k++) {
        int j = tid + k * 1024;
        det[k] = true;
        cw[k] = 0; cache[k] = 0u; rmA[k] = 0ull; rmB[k] = 0ull;
        if (j >= NLOC) continue;
        if ((removed[j >> 5] >> (j & 31)) & 1u) continue;     // dead -> done
        uint4 rv = *((const uint4*)&g_rowmask[((size_t)(b * NLOCP + j)) * 4]);
        rmA[k] = (unsigned long long)rv.x | ((unsigned long long)rv.y << 32);
        rmB[k] = (unsigned long long)rv.z | ((unsigned long long)rv.w << 32);
        int w;
        if (rmA[k])      w = __ffsll(rmA[k]) - 1;
        else if (rmB[k]) w = 64 + __ffsll(rmB[k]) - 1;
        else { atomicOr(&kept[j >> 5], 1u << (j & 31)); continue; }
        if (w < 64) rmA[k] &= rmA[k] - 1; else rmB[k] &= rmB[k] - 1;
        cw[k] = w;
        cache[k] = __ldg(M + (size_t)w * NLOCP + j);
        det[k] = false;
    }
    __syncthreads();

    // ---- rounds: monotone lattice -> stale reads safe; ONE barrier per round.
    int r = 0;
    while (true) {
        const int slot = r - (r / 3) * 3;
        int next = slot + 1; if (next == 3) next = 0;

#pragma unroll
        for (int k = 0; k < 4; k++) {
            if (det[k]) continue;
            int j = tid + k * 1024;

            unsigned raw = cache[k];
            int w = cw[k];
            if (raw & kept[w]) {
                atomicOr(&removed[j >> 5], 1u << (j & 31));
                det[k] = true; chg[slot] = 1;
                continue;
            }
            if (raw & ~removed[w]) continue;                  // still stalled

            // stall word fully removed: jump to next live word via bitmap
            bool progressed = false;
            while (true) {
                int nw2;
                if (rmA[k])      nw2 = __ffsll(rmA[k]) - 1;
                else if (rmB[k]) nw2 = 64 + __ffsll(rmB[k]) - 1;
                else {
                    atomicOr(&kept[j >> 5], 1u << (j & 31));
                    det[k] = true; progressed = true;
                    break;
                }
                if (nw2 < 64) rmA[k] &= rmA[k] - 1; else rmB[k] &= rmB[k] - 1;
                unsigned v = __ldg(M + (size_t)nw2 * NLOCP + j);
                if (v & kept[nw2]) {
                    atomicOr(&removed[j >> 5], 1u << (j & 31));
                    det[k] = true; progressed = true;
                    break;
                }
                if (v & ~removed[nw2]) {
                    cw[k] = nw2; cache[k] = v; progressed = true;
                    break;
                }
                // word fully removed -> keep jumping
            }
            if (progressed) chg[slot] = 1;
        }
        if (tid == 0) chg[next] = 0;
        __syncthreads();
        if (!chg[slot]) break;
        r++;
    }

    // ---- scatter surviving scores into prob channel 20
    float* prob = out;
    for (int p = tid; p < NLOC; p += 1024) {
        int o = g_sidx[base + p];
        float sc = g_ss[base + p];
        float v = (sc > 0.0f && ((kept[p >> 5] >> (p & 31)) & 1u)) ? sc : 0.0f;
        prob[((size_t)b * NLOC + o) * 21 + 20] = v;
    }
}

extern "C" void kernel_launch(void* const* d_in, const int* in_sizes, int n_in,
                              void* d_out, int out_size)
{
    (void)in_sizes; (void)n_in; (void)out_size;
    const float* x = (const float*)d_in[0];
    const float* im = (const float*)d_in[1];
    float* out = (float*)d_out;

    dim3 g1((NLOC + 127) / 128, BATCH);
    decode_kernel<<<g1, 128>>>(x, im, out);
    sort_kernel<<<BATCH, 1024>>>();
    dim3 g3(NW, (NW + 3) / 4, BATCH);
    mat_kernel<<<g3, 128>>>();
    reduce_kernel<<<BATCH, 1024>>>(out);
}

// round 10
// speedup vs baseline: 1.7310x; 1.0091x over previous
#include <cuda_runtime.h>
#include <math.h>

#define NCLS 20
#define NA 5
#define HH 26
#define WW 26
#define NLOC 3380      // NA*HH*WW
#define NLOCP 3392     // padded stride for matC
#define NPAD 4096
#define NW 106         // ceil(NLOC/32)
#define BATCH 16
#define NMS_TH 0.45f
#define K2 0.31034482758f   // 0.45/1.45
#define PRE_TH 0.005f
#define FEAT_STRIDE 32.0f

__constant__ float c_biases[10] = {1.08f, 1.19f, 3.42f, 4.41f, 6.63f, 11.38f,
                                   9.42f, 5.11f, 16.62f, 10.52f};

// ---- device scratch (static; no allocations) ----
__device__ float g_x1[BATCH * NLOC], g_y1[BATCH * NLOC];
__device__ float g_x2[BATCH * NLOC], g_y2[BATCH * NLOC];
__device__ float g_ka[BATCH * NLOC], g_score[BATCH * NLOC];
__device__ float4 g_sbox[BATCH * NLOC];          // sorted (x1,y1,x2,y2)
__device__ float g_ska[BATCH * NLOC], g_ss[BATCH * NLOC];
__device__ int g_sidx[BATCH * NLOC];
__device__ unsigned g_alive[BATCH * NW];
// column-major suppression matrix: matC[b][w][j] = i-word w suppressor bits of row j
__device__ unsigned g_matC[(size_t)BATCH * NW * NLOCP];   // ~23 MB
// per-row bitmap of NONZERO suppressor words (128 bits, words 0..105)
__device__ unsigned g_rowmask[(size_t)BATCH * NLOCP * 4];

// ============ kernel 1: decode (fully parallel) ============
__global__ void decode_kernel(const float* __restrict__ x,
                              const float* __restrict__ im_info,
                              float* __restrict__ out)
{
    const int b = blockIdx.y;
    const int loc = blockIdx.x * 128 + threadIdx.x;
    if (loc >= NLOC) return;

    // zero this batch's rowmask entry for rank==loc (replay-safe re-init)
    *((uint4*)&g_rowmask[((size_t)(b * NLOCP + loc)) * 4]) = make_uint4(0u, 0u, 0u, 0u);

    const float im_h = im_info[0];
    const float im_w = im_info[1];
    const float netw = WW * FEAT_STRIDE;
    const float neth = HH * FEAT_STRIDE;
    const bool cond = (netw / im_w) < (neth / im_h);
    const float new_w = cond ? netw : im_w * neth / im_h;
    const float new_h = cond ? im_h * netw / im_w : neth;

    float* prob = out;
    float* bbox = out + (size_t)BATCH * NLOC * 21;
    const float* xb = x + (size_t)b * 125 * (HH * WW);

    int a = loc / (HH * WW);
    int rem = loc - a * (HH * WW);
    int hh = rem / WW;
    int ww = rem - hh * WW;

    float tx = xb[(2 * a) * 676 + rem];
    float ty = xb[(2 * a + 1) * 676 + rem];
    float tw = xb[(10 + 2 * a) * 676 + rem];
    float th = xb[(11 + 2 * a) * 676 + rem];
    float to = xb[(20 + a) * 676 + rem];

    float obj = 1.0f / (1.0f + expf(-to));

    float cf[NCLS];
    float m = -INFINITY;
#pragma unroll
    for (int c = 0; c < NCLS; c++) {
        cf[c] = xb[(25 + 5 * c + a) * 676 + rem];
        m = fmaxf(m, cf[c]);
    }
    float sum = 0.0f;
#pragma unroll
    for (int c = 0; c < NCLS; c++) {
        cf[c] = expf(cf[c] - m);
        sum += cf[c];
    }
    float inv = obj / sum;
    float* pr = prob + ((size_t)b * NLOC + loc) * 21;
#pragma unroll
    for (int c = 0; c < NCLS; c++) pr[c] = cf[c] * inv;

    float sx = 1.0f / (1.0f + expf(-tx));
    float sy = 1.0f / (1.0f + expf(-ty));
    float bxv = ((float)ww + sx) / (float)WW;
    float byv = ((float)hh + sy) / (float)HH;
    float bwv = c_biases[2 * a] * expf(tw) / (float)WW;
    float bhv = c_biases[2 * a + 1] * expf(th) / (float)HH;

    bxv = (bxv - (netw - new_w) * 0.5f / netw) / (new_w / netw);
    byv = (byv - (neth - new_h) * 0.5f / neth) / (new_h / neth);
    bwv = bwv * (netw / new_w);
    bhv = bhv * (neth / new_h);

    float cx = bxv * im_w, cy = byv * im_h;
    float bw2 = bwv * im_w, bh2 = bhv * im_h;

    float4* bo = (float4*)(bbox + ((size_t)b * NLOC + loc) * 4);
    *bo = make_float4(cx, cy, bw2, bh2);

    float X1 = cx - bw2 * 0.5f, Y1 = cy - bh2 * 0.5f;
    float X2 = cx + bw2 * 0.5f, Y2 = cy + bh2 * 0.5f;
    int gi = b * NLOC + loc;
    g_x1[gi] = X1; g_y1[gi] = Y1;
    g_x2[gi] = X2; g_y2[gi] = Y2;
    g_ka[gi] = K2 * ((X2 - X1) * (Y2 - Y1));
    g_score[gi] = (obj < PRE_TH) ? 0.0f : obj;
}

// ============ kernel 2: per-batch bitonic sort on packed 64-bit keys ============
// key = (float_bits(score) << 32) | (0xFFFFFFFF - idx)
// uint64 descending == (score desc, idx asc); keys unique; padding = 0 sorts last.
__global__ void __launch_bounds__(1024, 1)
sort_kernel()
{
    __shared__ unsigned long long skey[NPAD];
    const int b = blockIdx.x;
    const int tid = threadIdx.x;
    const int base = b * NLOC;

    for (int p = tid; p < NLOC; p += 1024) {
        unsigned sb = __float_as_uint(g_score[base + p]);
        skey[p] = ((unsigned long long)sb << 32) | (0xFFFFFFFFu - (unsigned)p);
    }
    for (int p = NLOC + tid; p < NPAD; p += 1024)
        skey[p] = 0ull;
    __syncthreads();

    for (unsigned k = 2; k <= NPAD; k <<= 1) {
        for (unsigned j = k >> 1; j > 0; j >>= 1) {
            for (unsigned i = tid; i < NPAD; i += 1024) {
                unsigned ixj = i ^ j;
                if (ixj > i) {
                    unsigned long long ka = skey[i], kb = skey[ixj];
                    bool dirDesc = ((i & k) == 0);
                    if ((kb > ka) == dirDesc) {
                        skey[i] = kb;
                        skey[ixj] = ka;
                    }
                }
            }
            __syncthreads();
        }
    }

    for (int p = tid; p < NLOC; p += 1024) {
        unsigned long long key = skey[p];
        float sc = __uint_as_float((unsigned)(key >> 32));
        int o = (int)(0xFFFFFFFFu - (unsigned)key);
        g_ss[base + p] = sc;
        g_sidx[base + p] = o;
        g_sbox[base + p] = make_float4(g_x1[base + o], g_y1[base + o],
                                       g_x2[base + o], g_y2[base + o]);
        // dead boxes can never suppress: ka = +INF makes inter > kai+kaj false
        g_ska[base + p] = (sc > 0.0f) ? g_ka[base + o] : INFINITY;
    }
    __syncthreads();
    for (int chunk = 0; chunk < NPAD; chunk += 1024) {
        int p = chunk + tid;
        bool alive = (p < NLOC) && ((skey[p] >> 32) != 0ull);
        unsigned w = __ballot_sync(0xFFFFFFFFu, alive);
        int word = p >> 5;
        if ((tid & 31) == 0 && word < NW)
            g_alive[b * NW + word] = w;
    }
}

// ============ kernel 3: suppression matrix + per-row live-word bitmap ==========
__global__ void __launch_bounds__(128, 8)
mat_kernel()
{
    const int w = blockIdx.x;                       // i-word
    const int b = blockIdx.z;
    const int lane = threadIdx.x & 31;
    const int warpid = threadIdx.x >> 5;
    const int jword = blockIdx.y * 4 + warpid;      // j-word
    if (jword < w || jword >= NW) return;

    const int base = b * NLOC;
    const int i = w * 32 + lane;
    float4 ibx = make_float4(0.f, 0.f, 0.f, 0.f);
    float ika = INFINITY;
    if (i < NLOC) { ibx = g_sbox[base + i]; ika = g_ska[base + i]; }

    unsigned myword = 0u;
    const int jbase = jword * 32;

#pragma unroll 4
    for (int r = 0; r < 32; r++) {
        int j = jbase + r;
        if (j >= NLOC) break;                        // uniform
        float4 jb = __ldg(&g_sbox[base + j]);
        float jka = __ldg(&g_ska[base + j]);
        float iw = fminf(ibx.z, jb.z) - fmaxf(ibx.x, jb.x);
        float ih = fminf(ibx.w, jb.w) - fmaxf(ibx.y, jb.y);
        float inter = fmaxf(iw, 0.0f) * fmaxf(ih, 0.0f);
        bool sup = (inter > ika + jka) && (j > i);
        unsigned m = __ballot_sync(0xFFFFFFFFu, sup);
        if (lane == r) myword = m;
    }

    int j = jbase + lane;
    g_matC[((size_t)(b * NW + w)) * NLOCP + j] = myword;
    if (myword && j < NLOC)
        atomicOr(&g_rowmask[((size_t)(b * NLOCP + j)) * 4 + (w >> 5)],
                 1u << (w & 31));
}

// pop lowest live word from 128-bit bitmap held in two u64 regs
#define POPW(A, Bm, wvar) \
    do { if (A) { wvar = __ffsll(A) - 1; A &= A - 1; } \
         else   { wvar = 64 + __ffsll(Bm) - 1; Bm &= Bm - 1; } } while (0)

// ============ kernel 4: fixpoint with 3-deep register cache of live words ======
__global__ void __launch_bounds__(1024, 1)
reduce_kernel(float* __restrict__ out)
{
    __shared__ unsigned kept[NW];
    __shared__ unsigned removed[NW];
    __shared__ int chg[3];

    const int b = blockIdx.x;
    const int tid = threadIdx.x;
    const int base = b * NLOC;
    const unsigned* M = g_matC + (size_t)b * NW * NLOCP;   // M[w*NLOCP + j]

    for (int w = tid; w < NW; w += 1024) {
        kept[w] = 0u;
        removed[w] = ~g_alive[b * NW + w];   // dead boxes start removed
    }
    if (tid < 3) chg[tid] = 0;
    __syncthreads();

    // per-row state, 4 rows/thread:
    //  v0/v1/v2 : cached raw matC words (raw bits never change)
    //  wpk      : w0 | w1<<8 | w2<<16 | cnt<<24 | ovf<<27
    //  st       : 0..2 = cursor into cache; 4 = determined; 8 = overflow stall
    //  rmA/rmB  : remaining live-word bitmap beyond cache (overflow rows only)
    unsigned v0[4], v1[4], v2[4], wpk[4];
    int st[4];
    unsigned long long rmA[4], rmB[4];

    // ---- init: prefetch up to 3 live words with INDEPENDENT loads
#pragma unroll
    for (int k = 0; k < 4; k++) {
        int j = tid + k * 1024;
        st[k] = 4; wpk[k] = 0; v0[k] = v1[k] = v2[k] = 0u;
        rmA[k] = 0ull; rmB[k] = 0ull;
        if (j >= NLOC) continue;
        if ((removed[j >> 5] >> (j & 31)) & 1u) continue;     // dead -> done
        uint4 rv = *((const uint4*)&g_rowmask[((size_t)(b * NLOCP + j)) * 4]);
        unsigned long long A  = (unsigned long long)rv.x | ((unsigned long long)rv.y << 32);
        unsigned long long Bm = (unsigned long long)rv.z | ((unsigned long long)rv.w << 32);
        int w0 = 0, w1 = 0, w2 = 0, cnt = 0;
        if (A | Bm) { POPW(A, Bm, w0); cnt = 1;
            if (A | Bm) { POPW(A, Bm, w1); cnt = 2;
                if (A | Bm) { POPW(A, Bm, w2); cnt = 3; } } }
        if (cnt == 0) { atomicOr(&kept[j >> 5], 1u << (j & 31)); continue; }
        // independent loads (MLP)
        v0[k] = __ldg(M + (size_t)w0 * NLOCP + j);
        if (cnt > 1) v1[k] = __ldg(M + (size_t)w1 * NLOCP + j);
        if (cnt > 2) v2[k] = __ldg(M + (size_t)w2 * NLOCP + j);
        unsigned ovf = ((A | Bm) != 0ull) ? (1u << 27) : 0u;
        wpk[k] = (unsigned)w0 | ((unsigned)w1 << 8) | ((unsigned)w2 << 16)
               | ((unsigned)cnt << 24) | ovf;
        rmA[k] = A; rmB[k] = Bm;
        st[k] = 0;
    }
    __syncthreads();

    // ---- rounds: monotone lattice -> stale reads safe; ONE barrier per round.
    int r = 0;
    while (true) {
        const int slot = r - (r / 3) * 3;
        int next = slot + 1; if (next == 3) next = 0;

#pragma unroll
        for (int k = 0; k < 4; k++) {
            int s = st[k];
            if (s == 4) continue;
            int j = tid + k * 1024;
            unsigned wp = wpk[k];

            if (s < 4) {
                int w = (wp >> (8 * s)) & 0xFF;
                unsigned v = (s == 0) ? v0[k] : (s == 1) ? v1[k] : v2[k];
                if (v & kept[w]) {
                    atomicOr(&removed[j >> 5], 1u << (j & 31));
                    st[k] = 4; chg[slot] = 1; continue;
                }
                if (v & ~removed[w]) continue;                // stalled
                int cnt = (wp >> 24) & 7;
                bool decided = false;
                for (;;) {                                    // advance in cache
                    s++;
                    if (s >= cnt) break;
                    int wn = (wp >> (8 * s)) & 0xFF;
                    unsigned vn = (s == 1) ? v1[k] : v2[k];
                    if (vn & kept[wn]) {
                        atomicOr(&removed[j >> 5], 1u << (j & 31));
                        st[k] = 4; decided = true; break;
                    }
                    if (vn & ~removed[wn]) { st[k] = s; decided = true; break; }
                }
                if (!decided) {
                    if (!((wp >> 27) & 1u)) {
                        atomicOr(&kept[j >> 5], 1u << (j & 31));
                        st[k] = 4;
                    } else {
                        for (;;) {                            // overflow jump (rare)
                            if (!(rmA[k] | rmB[k])) {
                                atomicOr(&kept[j >> 5], 1u << (j & 31));
                                st[k] = 4; break;
                            }
                            int w3; POPW(rmA[k], rmB[k], w3);
                            unsigned v3 = __ldg(M + (size_t)w3 * NLOCP + j);
                            if (v3 & kept[w3]) {
                                atomicOr(&removed[j >> 5], 1u << (j & 31));
                                st[k] = 4; break;
                            }
                            if (v3 & ~removed[w3]) {
                                v0[k] = v3;
                                wpk[k] = (wp & 0xFFFFFF00u) | (unsigned)w3;
                                st[k] = 8; break;
                            }
                        }
                    }
                }
                chg[slot] = 1;
                continue;
            }

            // s == 8: overflow stall (current word in v0 / wpk[7:0])
            {
                int w = wp & 0xFF;
                unsigned v = v0[k];
                if (v & kept[w]) {
                    atomicOr(&removed[j >> 5], 1u << (j & 31));
                    st[k] = 4; chg[slot] = 1; continue;
                }
                if (v & ~removed[w]) continue;
                for (;;) {
                    if (!(rmA[k] | rmB[k])) {
                        atomicOr(&kept[j >> 5], 1u << (j & 31));
                        st[k] = 4; break;
                    }
                    int w3; POPW(rmA[k], rmB[k], w3);
                    unsigned v3 = __ldg(M + (size_t)w3 * NLOCP + j);
                    if (v3 & kept[w3]) {
                        atomicOr(&removed[j >> 5], 1u << (j & 31));
                        st[k] = 4; break;
                    }
                    if (v3 & ~removed[w3]) {
                        v0[k] = v3;
                        wpk[k] = (wp & 0xFFFFFF00u) | (unsigned)w3;
                        break;
                    }
                }
                chg[slot] = 1;
            }
        }
        if (tid == 0) chg[next] = 0;
        __syncthreads();
        if (!chg[slot]) break;
        r++;
    }

    // ---- scatter surviving scores into prob channel 20
    float* prob = out;
    for (int p = tid; p < NLOC; p += 1024) {
        int o = g_sidx[base + p];
        float sc = g_ss[base + p];
        float v = (sc > 0.0f && ((kept[p >> 5] >> (p & 31)) & 1u)) ? sc : 0.0f;
        prob[((size_t)b * NLOC + o) * 21 + 20] = v;
    }
}

extern "C" void kernel_launch(void* const* d_in, const int* in_sizes, int n_in,
                              void* d_out, int out_size)
{
    (void)in_sizes; (void)n_in; (void)out_size;
    const float* x = (const float*)d_in[0];
    const float* im = (const float*)d_in[1];
    float* out = (float*)d_out;

    dim3 g1((NLOC + 127) / 128, BATCH);
    decode_kernel<<<g1, 128>>>(x, im, out);
    sort_kernel<<<BATCH, 1024>>>();
    dim3 g3(NW, (NW + 3) / 4, BATCH);
    mat_kernel<<<g3, 128>>>();
    reduce_kernel<<<BATCH, 1024>>>(out);
}

// round 11
// speedup vs baseline: 1.7334x; 1.0014x over previous
#include <cuda_runtime.h>
#include <math.h>

#define NCLS 20
#define NA 5
#define HH 26
#define WW 26
#define NLOC 3380      // NA*HH*WW
#define NLOCP 3392     // padded stride for matC
#define NPAD 4096
#define NW 106         // ceil(NLOC/32)
#define BATCH 16
#define NMS_TH 0.45f
#define K2 0.31034482758f   // 0.45/1.45
#define PRE_TH 0.005f
#define FEAT_STRIDE 32.0f

__constant__ float c_biases[10] = {1.08f, 1.19f, 3.42f, 4.41f, 6.63f, 11.38f,
                                   9.42f, 5.11f, 16.62f, 10.52f};

// ---- device scratch (static; no allocations) ----
__device__ float g_x1[BATCH * NLOC], g_y1[BATCH * NLOC];
__device__ float g_x2[BATCH * NLOC], g_y2[BATCH * NLOC];
__device__ float g_ka[BATCH * NLOC], g_score[BATCH * NLOC];
__device__ float4 g_sbox[BATCH * NLOC];          // sorted (x1,y1,x2,y2)
__device__ float g_ska[BATCH * NLOC], g_ss[BATCH * NLOC];
__device__ int g_sidx[BATCH * NLOC];
__device__ unsigned g_alive[BATCH * NW];
// column-major suppression matrix: matC[b][w][j] = i-word w suppressor bits of row j
__device__ unsigned g_matC[(size_t)BATCH * NW * NLOCP];   // ~23 MB
// per-row bitmap of NONZERO suppressor words (128 bits, words 0..105)
__device__ unsigned g_rowmask[(size_t)BATCH * NLOCP * 4];

// ============ kernel 1: decode (fully parallel) ============
__global__ void decode_kernel(const float* __restrict__ x,
                              const float* __restrict__ im_info,
                              float* __restrict__ out)
{
    const int b = blockIdx.y;
    const int loc = blockIdx.x * 128 + threadIdx.x;
    if (loc >= NLOC) return;

    // zero this batch's rowmask entry for rank==loc (replay-safe re-init)
    *((uint4*)&g_rowmask[((size_t)(b * NLOCP + loc)) * 4]) = make_uint4(0u, 0u, 0u, 0u);

    const float im_h = im_info[0];
    const float im_w = im_info[1];
    const float netw = WW * FEAT_STRIDE;
    const float neth = HH * FEAT_STRIDE;
    const bool cond = (netw / im_w) < (neth / im_h);
    const float new_w = cond ? netw : im_w * neth / im_h;
    const float new_h = cond ? im_h * netw / im_w : neth;

    float* prob = out;
    float* bbox = out + (size_t)BATCH * NLOC * 21;
    const float* xb = x + (size_t)b * 125 * (HH * WW);

    int a = loc / (HH * WW);
    int rem = loc - a * (HH * WW);
    int hh = rem / WW;
    int ww = rem - hh * WW;

    float tx = xb[(2 * a) * 676 + rem];
    float ty = xb[(2 * a + 1) * 676 + rem];
    float tw = xb[(10 + 2 * a) * 676 + rem];
    float th = xb[(11 + 2 * a) * 676 + rem];
    float to = xb[(20 + a) * 676 + rem];

    float obj = 1.0f / (1.0f + expf(-to));

    float cf[NCLS];
    float m = -INFINITY;
#pragma unroll
    for (int c = 0; c < NCLS; c++) {
        cf[c] = xb[(25 + 5 * c + a) * 676 + rem];
        m = fmaxf(m, cf[c]);
    }
    float sum = 0.0f;
#pragma unroll
    for (int c = 0; c < NCLS; c++) {
        cf[c] = expf(cf[c] - m);
        sum += cf[c];
    }
    float inv = obj / sum;
    float* pr = prob + ((size_t)b * NLOC + loc) * 21;
#pragma unroll
    for (int c = 0; c < NCLS; c++) pr[c] = cf[c] * inv;

    float sx = 1.0f / (1.0f + expf(-tx));
    float sy = 1.0f / (1.0f + expf(-ty));
    float bxv = ((float)ww + sx) / (float)WW;
    float byv = ((float)hh + sy) / (float)HH;
    float bwv = c_biases[2 * a] * expf(tw) / (float)WW;
    float bhv = c_biases[2 * a + 1] * expf(th) / (float)HH;

    bxv = (bxv - (netw - new_w) * 0.5f / netw) / (new_w / netw);
    byv = (byv - (neth - new_h) * 0.5f / neth) / (new_h / neth);
    bwv = bwv * (netw / new_w);
    bhv = bhv * (neth / new_h);

    float cx = bxv * im_w, cy = byv * im_h;
    float bw2 = bwv * im_w, bh2 = bhv * im_h;

    float4* bo = (float4*)(bbox + ((size_t)b * NLOC + loc) * 4);
    *bo = make_float4(cx, cy, bw2, bh2);

    float X1 = cx - bw2 * 0.5f, Y1 = cy - bh2 * 0.5f;
    float X2 = cx + bw2 * 0.5f, Y2 = cy + bh2 * 0.5f;
    int gi = b * NLOC + loc;
    g_x1[gi] = X1; g_y1[gi] = Y1;
    g_x2[gi] = X2; g_y2[gi] = Y2;
    g_ka[gi] = K2 * ((X2 - X1) * (Y2 - Y1));
    g_score[gi] = (obj < PRE_TH) ? 0.0f : obj;
}

// ============ kernel 2: per-batch bitonic sort on packed 64-bit keys ============
// key = (float_bits(score) << 32) | (0xFFFFFFFF - idx)
// uint64 descending == (score desc, idx asc); keys unique; padding = 0 sorts last.
__global__ void __launch_bounds__(1024, 1)
sort_kernel()
{
    __shared__ unsigned long long skey[NPAD];
    const int b = blockIdx.x;
    const int tid = threadIdx.x;
    const int base = b * NLOC;

    for (int p = tid; p < NLOC; p += 1024) {
        unsigned sb = __float_as_uint(g_score[base + p]);
        skey[p] = ((unsigned long long)sb << 32) | (0xFFFFFFFFu - (unsigned)p);
    }
    for (int p = NLOC + tid; p < NPAD; p += 1024)
        skey[p] = 0ull;
    __syncthreads();

    for (unsigned k = 2; k <= NPAD; k <<= 1) {
        for (unsigned j = k >> 1; j > 0; j >>= 1) {
            for (unsigned i = tid; i < NPAD; i += 1024) {
                unsigned ixj = i ^ j;
                if (ixj > i) {
                    unsigned long long ka = skey[i], kb = skey[ixj];
                    bool dirDesc = ((i & k) == 0);
                    if ((kb > ka) == dirDesc) {
                        skey[i] = kb;
                        skey[ixj] = ka;
                    }
                }
            }
            __syncthreads();
        }
    }

    for (int p = tid; p < NLOC; p += 1024) {
        unsigned long long key = skey[p];
        float sc = __uint_as_float((unsigned)(key >> 32));
        int o = (int)(0xFFFFFFFFu - (unsigned)key);
        g_ss[base + p] = sc;
        g_sidx[base + p] = o;
        g_sbox[base + p] = make_float4(g_x1[base + o], g_y1[base + o],
                                       g_x2[base + o], g_y2[base + o]);
        // dead boxes can never suppress: ka = +INF makes inter > kai+kaj false
        g_ska[base + p] = (sc > 0.0f) ? g_ka[base + o] : INFINITY;
    }
    __syncthreads();
    for (int chunk = 0; chunk < NPAD; chunk += 1024) {
        int p = chunk + tid;
        bool alive = (p < NLOC) && ((skey[p] >> 32) != 0ull);
        unsigned w = __ballot_sync(0xFFFFFFFFu, alive);
        int word = p >> 5;
        if ((tid & 31) == 0 && word < NW)
            g_alive[b * NW + word] = w;
    }
}

// ============ kernel 3: suppression matrix + per-row live-word bitmap ==========
__global__ void __launch_bounds__(128, 8)
mat_kernel()
{
    const int w = blockIdx.x;                       // i-word
    const int b = blockIdx.z;
    const int lane = threadIdx.x & 31;
    const int warpid = threadIdx.x >> 5;
    const int jword = blockIdx.y * 4 + warpid;      // j-word
    if (jword < w || jword >= NW) return;

    const int base = b * NLOC;
    const int i = w * 32 + lane;
    float4 ibx = make_float4(0.f, 0.f, 0.f, 0.f);
    float ika = INFINITY;
    if (i < NLOC) { ibx = g_sbox[base + i]; ika = g_ska[base + i]; }

    unsigned myword = 0u;
    const int jbase = jword * 32;

#pragma unroll 4
    for (int r = 0; r < 32; r++) {
        int j = jbase + r;
        if (j >= NLOC) break;                        // uniform
        float4 jb = __ldg(&g_sbox[base + j]);
        float jka = __ldg(&g_ska[base + j]);
        float iw = fminf(ibx.z, jb.z) - fmaxf(ibx.x, jb.x);
        float ih = fminf(ibx.w, jb.w) - fmaxf(ibx.y, jb.y);
        float inter = fmaxf(iw, 0.0f) * fmaxf(ih, 0.0f);
        bool sup = (inter > ika + jka) && (j > i);
        unsigned m = __ballot_sync(0xFFFFFFFFu, sup);
        if (lane == r) myword = m;
    }

    int j = jbase + lane;
    g_matC[((size_t)(b * NW + w)) * NLOCP + j] = myword;
    if (myword && j < NLOC)
        atomicOr(&g_rowmask[((size_t)(b * NLOCP + j)) * 4 + (w >> 5)],
                 1u << (w & 31));
}

// pop lowest live word from 128-bit bitmap held in two u64 regs
#define POPW(A, Bm, wvar) \
    do { if (A) { wvar = __ffsll(A) - 1; A &= A - 1; } \
         else   { wvar = 64 + __ffsll(Bm) - 1; Bm &= Bm - 1; } } while (0)

// ============ kernel 4: bit-level fixpoint — check ALL cached words per round ==
__global__ void __launch_bounds__(1024, 1)
reduce_kernel(float* __restrict__ out)
{
    __shared__ unsigned kept[NW];
    __shared__ unsigned removed[NW];
    __shared__ int chg[3];

    const int b = blockIdx.x;
    const int tid = threadIdx.x;
    const int base = b * NLOC;
    const unsigned* M = g_matC + (size_t)b * NW * NLOCP;   // M[w*NLOCP + j]

    for (int w = tid; w < NW; w += 1024) {
        kept[w] = 0u;
        removed[w] = ~g_alive[b * NW + w];   // dead boxes start removed
    }
    if (tid < 3) chg[tid] = 0;
    __syncthreads();

    // per-row state, 4 rows/thread:
    //  v0/v1/v2 : cached raw matC words (raw bits never change)
    //  wpk      : w0 | w1<<8 | w2<<16
    //  pend     : bitmask {1,2,4} of cached words still pending (0 + !det -> drain)
    //  det      : decided
    //  rmA/rmB  : remaining live-word bitmap beyond cache (overflow rows only)
    unsigned v0[4], v1[4], v2[4], wpk[4];
    int pend[4];
    bool det[4];
    unsigned long long rmA[4], rmB[4];

    // ---- init: prefetch up to 3 live words with INDEPENDENT loads
#pragma unroll
    for (int k = 0; k < 4; k++) {
        int j = tid + k * 1024;
        det[k] = true; pend[k] = 0; wpk[k] = 0;
        v0[k] = v1[k] = v2[k] = 0u;
        rmA[k] = 0ull; rmB[k] = 0ull;
        if (j >= NLOC) continue;
        if ((removed[j >> 5] >> (j & 31)) & 1u) continue;     // dead -> done
        uint4 rv = *((const uint4*)&g_rowmask[((size_t)(b * NLOCP + j)) * 4]);
        unsigned long long A  = (unsigned long long)rv.x | ((unsigned long long)rv.y << 32);
        unsigned long long Bm = (unsigned long long)rv.z | ((unsigned long long)rv.w << 32);
        int w0 = 0, w1 = 0, w2 = 0, cnt = 0;
        if (A | Bm) { POPW(A, Bm, w0); cnt = 1;
            if (A | Bm) { POPW(A, Bm, w1); cnt = 2;
                if (A | Bm) { POPW(A, Bm, w2); cnt = 3; } } }
        if (cnt == 0) { atomicOr(&kept[j >> 5], 1u << (j & 31)); continue; }
        // independent loads (MLP)
        v0[k] = __ldg(M + (size_t)w0 * NLOCP + j);
        if (cnt > 1) v1[k] = __ldg(M + (size_t)w1 * NLOCP + j);
        if (cnt > 2) v2[k] = __ldg(M + (size_t)w2 * NLOCP + j);
        wpk[k] = (unsigned)w0 | ((unsigned)w1 << 8) | ((unsigned)w2 << 16);
        rmA[k] = A; rmB[k] = Bm;
        pend[k] = (1 << cnt) - 1;
        det[k] = false;
    }
    __syncthreads();

    // ---- rounds: monotone lattice -> stale reads safe; ONE barrier per round.
    int r = 0;
    while (true) {
        const int slot = r - (r / 3) * 3;
        int next = slot + 1; if (next == 3) next = 0;

#pragma unroll
        for (int k = 0; k < 4; k++) {
            if (det[k]) continue;
            int j = tid + k * 1024;
            unsigned wp = wpk[k];
            int p = pend[k];
            bool dec = false;

            // check every still-pending cached word (bit-level dependency)
            if (p & 1) {
                int w = wp & 0xFF;
                if (v0[k] & kept[w]) {
                    atomicOr(&removed[j >> 5], 1u << (j & 31)); dec = true;
                } else if (!(v0[k] & ~removed[w])) p &= ~1;
            }
            if (!dec && (p & 2)) {
                int w = (wp >> 8) & 0xFF;
                if (v1[k] & kept[w]) {
                    atomicOr(&removed[j >> 5], 1u << (j & 31)); dec = true;
                } else if (!(v1[k] & ~removed[w])) p &= ~2;
            }
            if (!dec && (p & 4)) {
                int w = (wp >> 16) & 0xFF;
                if (v2[k] & kept[w]) {
                    atomicOr(&removed[j >> 5], 1u << (j & 31)); dec = true;
                } else if (!(v2[k] & ~removed[w])) p &= ~4;
            }

            if (!dec && p == 0) {
                // drain overflow bitmap (rare: rows with >3 live words)
                for (;;) {
                    if (!(rmA[k] | rmB[k])) {
                        atomicOr(&kept[j >> 5], 1u << (j & 31));
                        dec = true; break;
                    }
                    int w3; POPW(rmA[k], rmB[k], w3);
                    unsigned v3 = __ldg(M + (size_t)w3 * NLOCP + j);
                    if (v3 & kept[w3]) {
                        atomicOr(&removed[j >> 5], 1u << (j & 31));
                        dec = true; break;
                    }
                    if (v3 & ~removed[w3]) {       // live again: park in slot 0
                        v0[k] = v3;
                        wpk[k] = (wp & 0xFFFFFF00u) | (unsigned)w3;
                        p = 1; break;
                    }
                }
            }

            if (dec) { det[k] = true; chg[slot] = 1; }
            else if (p != pend[k]) { pend[k] = p; chg[slot] = 1; }
        }
        if (tid == 0) chg[next] = 0;
        __syncthreads();
        if (!chg[slot]) break;
        r++;
    }

    // ---- scatter surviving scores into prob channel 20
    float* prob = out;
    for (int p = tid; p < NLOC; p += 1024) {
        int o = g_sidx[base + p];
        float sc = g_ss[base + p];
        float v = (sc > 0.0f && ((kept[p >> 5] >> (p & 31)) & 1u)) ? sc : 0.0f;
        prob[((size_t)b * NLOC + o) * 21 + 20] = v;
    }
}

extern "C" void kernel_launch(void* const* d_in, const int* in_sizes, int n_in,
                              void* d_out, int out_size)
{
    (void)in_sizes; (void)n_in; (void)out_size;
    const float* x = (const float*)d_in[0];
    const float* im = (const float*)d_in[1];
    float* out = (float*)d_out;

    dim3 g1((NLOC + 127) / 128, BATCH);
    decode_kernel<<<g1, 128>>>(x, im, out);
    sort_kernel<<<BATCH, 1024>>>();
    dim3 g3(NW, (NW + 3) / 4, BATCH);
    mat_kernel<<<g3, 128>>>();
    reduce_kernel<<<BATCH, 1024>>>(out);
}